// round 5
// baseline (speedup 1.0000x reference)
#include <cuda_runtime.h>
#include <cstdint>

// BidirectionalSoftmax: B=8, L1=L2=2048, TAU=0.5, EPS=1e-8
// No-max softmax (|y| bounded -> exp2 never overflows fp32):
//   e = exp2(sim * (1/TAU)*log2 e);  out = sqrt(EPS + e*e*inv_rowsum*inv_colsum)
//
//   k_stats : 512 uniform CTAs (64 row-slabs x 8 b), each covers all 2048 cols.
//             Produces col-sum partials AND final 1/row_sum (fused, same read).
//   k_merge : fold 64 slab partials -> 1/col_sum
//   k_out   : pure streaming elementwise; CTA = 2 rows, thread = 16 elems.

#define NB    8
#define NL    2048
#define NSLAB 64
#define RPS   32                      /* rows per slab */
#define SCALEV 2.8853900817779268f    /* (1/0.5) * log2(e) */
#define EPSV  1e-8f

__device__ float g_cps[NB * NSLAB * NL];  // partial col sums of exp2(y)
__device__ float g_ics[NB * NL];          // 1/col_sum
__device__ float g_irs[NB * NL];          // 1/row_sum (valid rows only)

__device__ __forceinline__ float ex2f(float x) {
    float r; asm("ex2.approx.f32 %0, %1;" : "=f"(r) : "f"(x)); return r;
}
__device__ __forceinline__ float sqrtap(float x) {
    float r; asm("sqrt.approx.f32 %0, %1;" : "=f"(r) : "f"(x)); return r;
}

// ---------------------------------------------------------------------------
// Pass 1: col-sum partials + final 1/row_sum. grid=(64,8), block=256.
// Thread owns cols [4t,4t+4) (A, always valid: len2>=1024) and [1024+4t,...) (B).
// ---------------------------------------------------------------------------
__global__ void __launch_bounds__(256, 4) k_stats(const float* __restrict__ sim,
                                                  const int*   __restrict__ len) {
    int slab = blockIdx.x, b = blockIdx.y;
    int t = threadIdx.x;
    int len1 = __ldg(&len[2 * b]);
    int len2 = __ldg(&len[2 * b + 1]);
    int r0 = slab * RPS;
    int n = min(r0 + RPS, len1) - r0;          // rows this CTA owns (may be <=0)

    __shared__ float srow[RPS * 256];          // 32 KB: per-(row, thread) partial

    int nvB = len2 - (1024 + 4 * t);
    bool wB = nvB > 0, k1 = nvB > 1, k2 = nvB > 2, k3 = nvB > 3;

    float a0 = 0.f, a1 = 0.f, a2 = 0.f, a3 = 0.f;   // col sums, chunk A
    float c0 = 0.f, c1 = 0.f, c2 = 0.f, c3 = 0.f;   // col sums, chunk B

    if (n > 0) {
        const float4* pA = reinterpret_cast<const float4*>(sim)
                         + ((size_t)b << 20) + ((size_t)r0 << 9) + t;
        int r = 0;
        for (; r + 4 <= n; r += 4) {
            float4 vA[4], vB[4];
#pragma unroll
            for (int u = 0; u < 4; u++) vA[u] = pA[u * 512];
#pragma unroll
            for (int u = 0; u < 4; u++)
                vB[u] = wB ? pA[u * 512 + 256] : make_float4(0.f, 0.f, 0.f, 0.f);
            pA += 4 * 512;
#pragma unroll
            for (int u = 0; u < 4; u++) {
                float eA0 = ex2f(vA[u].x * SCALEV), eA1 = ex2f(vA[u].y * SCALEV);
                float eA2 = ex2f(vA[u].z * SCALEV), eA3 = ex2f(vA[u].w * SCALEV);
                float eB0 = wB ? ex2f(vB[u].x * SCALEV) : 0.f;
                float eB1 = k1 ? ex2f(vB[u].y * SCALEV) : 0.f;
                float eB2 = k2 ? ex2f(vB[u].z * SCALEV) : 0.f;
                float eB3 = k3 ? ex2f(vB[u].w * SCALEV) : 0.f;
                a0 += eA0; a1 += eA1; a2 += eA2; a3 += eA3;
                c0 += eB0; c1 += eB1; c2 += eB2; c3 += eB3;
                srow[(r + u) * 256 + t] =
                    ((eA0 + eA1) + (eA2 + eA3)) + ((eB0 + eB1) + (eB2 + eB3));
            }
        }
        for (; r < n; r++) {
            float4 vA = pA[0];
            float4 vB = wB ? pA[256] : make_float4(0.f, 0.f, 0.f, 0.f);
            pA += 512;
            float eA0 = ex2f(vA.x * SCALEV), eA1 = ex2f(vA.y * SCALEV);
            float eA2 = ex2f(vA.z * SCALEV), eA3 = ex2f(vA.w * SCALEV);
            float eB0 = wB ? ex2f(vB.x * SCALEV) : 0.f;
            float eB1 = k1 ? ex2f(vB.y * SCALEV) : 0.f;
            float eB2 = k2 ? ex2f(vB.z * SCALEV) : 0.f;
            float eB3 = k3 ? ex2f(vB.w * SCALEV) : 0.f;
            a0 += eA0; a1 += eA1; a2 += eA2; a3 += eA3;
            c0 += eB0; c1 += eB1; c2 += eB2; c3 += eB3;
            srow[r * 256 + t] =
                ((eA0 + eA1) + (eA2 + eA3)) + ((eB0 + eB1) + (eB2 + eB3));
        }
    }

    // col partials (always stored; zero for inactive slabs / masked cols)
    size_t base = (size_t)(b * NSLAB + slab) << 11;
    *reinterpret_cast<float4*>(&g_cps[base + 4 * t])        = make_float4(a0, a1, a2, a3);
    *reinterpret_cast<float4*>(&g_cps[base + 1024 + 4 * t]) = make_float4(c0, c1, c2, c3);

    __syncthreads();

    // final row sums: warp w reduces rows w*4 .. w*4+3
    int wid = t >> 5, lane = t & 31;
#pragma unroll
    for (int q = 0; q < 4; q++) {
        int rr = wid * 4 + q;
        if (rr < n) {
            const float* sp = &srow[rr * 256];
            float s = ((sp[lane] + sp[lane + 32]) + (sp[lane + 64] + sp[lane + 96]))
                    + ((sp[lane + 128] + sp[lane + 160]) + (sp[lane + 192] + sp[lane + 224]));
#pragma unroll
            for (int o = 16; o; o >>= 1) s += __shfl_xor_sync(0xffffffffu, s, o);
            if (lane == 0) g_irs[(b << 11) + r0 + rr] = 1.0f / s;
        }
    }
}

// ---------------------------------------------------------------------------
// Pass 1b: fold 64 slab partials per (batch, column) -> 1/col_sum.
// ---------------------------------------------------------------------------
__global__ void __launch_bounds__(256) k_merge() {
    int idx = blockIdx.x * 256 + threadIdx.x;     // b*NL + j
    int b = idx >> 11, j = idx & (NL - 1);

    float acc = 0.f;
#pragma unroll
    for (int s = 0; s < NSLAB; s++)
        acc += g_cps[((size_t)(b * NSLAB + s) << 11) + j];
    g_ics[idx] = acc > 0.f ? (1.0f / acc) : 0.f;
}

// ---------------------------------------------------------------------------
// Pass 2: pure streaming. CTA = 2 rows (256 thr), thread = 16 contiguous
// elements (4 float4 in / 4 float4 out). No barriers, no reductions.
// ---------------------------------------------------------------------------
__global__ void __launch_bounds__(256) k_out(const float* __restrict__ sim,
                                             const int*   __restrict__ len,
                                             float*       __restrict__ out) {
    int cta = blockIdx.x;                   // 0 .. NB*NL/2-1
    int b = cta >> 10;
    int i = ((cta & 1023) << 1) + (threadIdx.x >> 7);
    int j0 = (threadIdx.x & 127) << 4;
    size_t base = ((size_t)b << 22) + ((size_t)i << 11) + j0;
    float4* o = reinterpret_cast<float4*>(out + base);

    int len1 = __ldg(&len[2 * b]);
    int len2 = __ldg(&len[2 * b + 1]);
    if (i >= len1 || j0 >= len2) {
        float4 z = make_float4(0.f, 0.f, 0.f, 0.f);
        o[0] = z; o[1] = z; o[2] = z; o[3] = z;
        return;
    }

    float irs = __ldg(&g_irs[(b << 11) + i]);
    const float4* p  = reinterpret_cast<const float4*>(sim + base);
    const float4* ic = reinterpret_cast<const float4*>(g_ics + (b << 11) + j0);

    float4 v[4], c[4];
#pragma unroll
    for (int u = 0; u < 4; u++) v[u] = p[u];
#pragma unroll
    for (int u = 0; u < 4; u++) c[u] = __ldg(&ic[u]);

    int nv = len2 - j0;                     // > 0
#pragma unroll
    for (int u = 0; u < 4; u++) {
        float e0 = ex2f(v[u].x * SCALEV), e1 = ex2f(v[u].y * SCALEV);
        float e2 = ex2f(v[u].z * SCALEV), e3 = ex2f(v[u].w * SCALEV);
        float4 r;
        r.x = (4 * u + 0 < nv) ? sqrtap(fmaf(e0 * e0 * irs, c[u].x, EPSV)) : 0.f;
        r.y = (4 * u + 1 < nv) ? sqrtap(fmaf(e1 * e1 * irs, c[u].y, EPSV)) : 0.f;
        r.z = (4 * u + 2 < nv) ? sqrtap(fmaf(e2 * e2 * irs, c[u].z, EPSV)) : 0.f;
        r.w = (4 * u + 3 < nv) ? sqrtap(fmaf(e3 * e3 * irs, c[u].w, EPSV)) : 0.f;
        o[u] = r;
    }
}

// ---------------------------------------------------------------------------
extern "C" void kernel_launch(void* const* d_in, const int* in_sizes, int n_in,
                              void* d_out, int out_size) {
    const float* sim = (const float*)d_in[0];
    const int*   len = (const int*)d_in[1];
    if (n_in >= 2 && in_sizes[0] == 16) {   // defensive: swapped order
        sim = (const float*)d_in[1];
        len = (const int*)d_in[0];
    }
    float* out = (float*)d_out;

    dim3 g1(NSLAB, NB);                       // 512 uniform CTAs
    k_stats<<<g1, 256>>>(sim, len);
    k_merge<<<(NB * NL) / 256, 256>>>();      // 64 CTAs
    k_out<<<NB * NL / 2, 256>>>(sim, len, out); // 8192 CTAs
}